// round 13
// baseline (speedup 1.0000x reference)
#include <cuda_runtime.h>
#include <cuda_bf16.h>
#include <cstdint>

// ---------------- problem constants ----------------
#define BHALF 4096
#define NROWS 8192
#define DDIM  1024
#define INVT  10.0f
#define Y_SCALE 14.4269504088896341f   // INVT * log2(e)

// ---------------- tiling ----------------
#define KC 64                 // K elems per pipeline stage
#define ROW_BYTES 144         // 64 bf16 = 128B + 16B pad
#define A_BYTES (128 * ROW_BYTES)          // 18432
#define STAGE_BYTES (2 * A_BYTES)          // 36864
#define NSTAGES 3
#define SMEM_TOTAL (NSTAGES * STAGE_BYTES) // 110592
#define NBLK 64               // 8192 / 128
// jobs: 16 half-tiles (tiles rb=0,cb=1..8 split by column) + 2072 singles
#define NJOBS 2088

__device__ __align__(16) __nv_bfloat16 g_fn[NROWS * DDIM];  // normalized bf16 (16MB)
__device__ float g_rowsum[NROWS];
__device__ float g_pos[NROWS];

// ---------------------------------------------------------------------------
__device__ __forceinline__ float fexp2f(float y) {
    float t = y + 12582912.0f;
    int   i = __float_as_int(t);
    float f = y - (t - 12582912.0f);
    float p = 1.33335581e-3f;
    p = fmaf(p, f, 9.61812910e-3f);
    p = fmaf(p, f, 5.55041086e-2f);
    p = fmaf(p, f, 2.40226507e-1f);
    p = fmaf(p, f, 6.93147182e-1f);
    p = fmaf(p, f, 1.0f);
    return p * __int_as_float((i + (127 - 0x4B400000)) << 23);
}

// ---------------------------------------------------------------------------
// Kernel 1: row L2-normalize -> bf16; also zeroes accumulators and out[0].
// ---------------------------------------------------------------------------
__global__ void __launch_bounds__(128) norm_kernel(const float* __restrict__ v1,
                                                   const float* __restrict__ v2,
                                                   float* __restrict__ out) {
    const int lane = threadIdx.x & 31;
    const int row  = blockIdx.x * 4 + (threadIdx.x >> 5);
    const float* src = (row < BHALF) ? (v1 + (size_t)row * DDIM)
                                     : (v2 + (size_t)(row - BHALF) * DDIM);
    const float4* src4 = reinterpret_cast<const float4*>(src);

    float4 u[4], w[4];
    float ss = 0.0f;
    #pragma unroll
    for (int i = 0; i < 4; i++) {
        u[i] = src4[lane * 2 + i * 64];
        w[i] = src4[lane * 2 + i * 64 + 1];
        ss += u[i].x*u[i].x + u[i].y*u[i].y + u[i].z*u[i].z + u[i].w*u[i].w;
        ss += w[i].x*w[i].x + w[i].y*w[i].y + w[i].z*w[i].z + w[i].w*w[i].w;
    }
    #pragma unroll
    for (int o = 16; o; o >>= 1) ss += __shfl_xor_sync(0xFFFFFFFFu, ss, o);
    float scale = 1.0f / fmaxf(sqrtf(ss), 1e-12f);

    uint4* dst = reinterpret_cast<uint4*>(g_fn + (size_t)row * DDIM);
    #pragma unroll
    for (int i = 0; i < 4; i++) {
        __nv_bfloat162 h0, h1, h2, h3;
        h0.x = __float2bfloat16(u[i].x*scale); h0.y = __float2bfloat16(u[i].y*scale);
        h1.x = __float2bfloat16(u[i].z*scale); h1.y = __float2bfloat16(u[i].w*scale);
        h2.x = __float2bfloat16(w[i].x*scale); h2.y = __float2bfloat16(w[i].y*scale);
        h3.x = __float2bfloat16(w[i].z*scale); h3.y = __float2bfloat16(w[i].w*scale);
        uint4 o4;
        o4.x = *reinterpret_cast<unsigned*>(&h0);
        o4.y = *reinterpret_cast<unsigned*>(&h1);
        o4.z = *reinterpret_cast<unsigned*>(&h2);
        o4.w = *reinterpret_cast<unsigned*>(&h3);
        dst[lane + i * 32] = o4;
    }
    if (lane == 0) { g_rowsum[row] = 0.0f; g_pos[row] = 0.0f; }
    if (row == 0 && lane == 0) out[0] = 0.0f;
}

// ---------------------------------------------------------------------------
// PTX helpers
// ---------------------------------------------------------------------------
__device__ __forceinline__ void cp_async16(unsigned dst, const void* src) {
    asm volatile("cp.async.cg.shared.global [%0], [%1], 16;" :: "r"(dst), "l"(src) : "memory");
}
__device__ __forceinline__ void cp_commit() {
    asm volatile("cp.async.commit_group;" ::: "memory");
}
__device__ __forceinline__ void ldmatrix_x4(unsigned& r0, unsigned& r1,
                                            unsigned& r2, unsigned& r3, unsigned addr) {
    asm volatile("ldmatrix.sync.aligned.m8n8.x4.shared.b16 {%0,%1,%2,%3}, [%4];"
                 : "=r"(r0), "=r"(r1), "=r"(r2), "=r"(r3) : "r"(addr));
}
__device__ __forceinline__ void mma_bf16(float& d0, float& d1, float& d2, float& d3,
                                         unsigned a0, unsigned a1, unsigned a2, unsigned a3,
                                         unsigned b0, unsigned b1) {
    asm volatile("mma.sync.aligned.m16n8k16.row.col.f32.bf16.bf16.f32 "
                 "{%0,%1,%2,%3}, {%4,%5,%6,%7}, {%8,%9}, {%0,%1,%2,%3};"
                 : "+f"(d0), "+f"(d1), "+f"(d2), "+f"(d3)
                 : "r"(a0), "r"(a1), "r"(a2), "r"(a3), "r"(b0), "r"(b1));
}

// A half-chunk: 4 cp.async of 16B (128 rows)
__device__ __forceinline__ void load_A(unsigned dstbase, const char* pA) {
    #pragma unroll
    for (int it = 0; it < 4; it++)
        cp_async16(dstbase + it * (32 * ROW_BYTES), pA + (size_t)it * 65536);
}
// B half-chunk: NF cp.async of 16B (NF*32 rows)
template <int NF>
__device__ __forceinline__ void load_B(unsigned dstbase, const char* pB) {
    #pragma unroll
    for (int it = 0; it < NF; it++)
        cp_async16(dstbase + A_BYTES + it * (32 * ROW_BYTES), pB + (size_t)it * 65536);
}

// ---------------------------------------------------------------------------
// Tile runner. NF = n-fragments per warp: 4 => full 128-col tile,
// 2 => half tile (64 cols starting at col_off). mirror: add col sums to cb rows.
// ---------------------------------------------------------------------------
template <int NF>
__device__ __forceinline__ void run_tile(int rb, int cb, int col_off, bool mirror,
                                         unsigned smem_base, int tid, int lane,
                                         int wm, int wn) {
    const int rA   = tid >> 3;
    const int p16  = (tid & 7) * 16;
    const char* gA = (const char*)g_fn
                   + ((size_t)(rb * 128 + rA) * DDIM) * 2 + p16;
    const char* gB = (const char*)g_fn
                   + ((size_t)(cb * 128 + col_off + rA) * DDIM) * 2 + p16;
    const unsigned ldst = smem_base + rA * ROW_BYTES + p16;

    const unsigned a_base = smem_base + (wm*32 + (lane & 15)) * ROW_BYTES + (lane >> 4) * 16;
    const unsigned b_base = smem_base + A_BYTES
                          + (wn*(NF*16) + (lane & 7) + ((lane >> 4) << 3)) * ROW_BYTES
                          + ((lane >> 3) & 1) * 16;

    float acc[2][2*NF][4];
    #pragma unroll
    for (int mf = 0; mf < 2; mf++)
        #pragma unroll
        for (int j = 0; j < 2*NF; j++)
            #pragma unroll
            for (int e = 0; e < 4; e++) acc[mf][j][e] = 0.0f;

    const int NCHUNK = DDIM / KC;    // 16
    load_A(ldst + 0*STAGE_BYTES, gA);
    load_B<NF>(ldst + 0*STAGE_BYTES, gB);       cp_commit();
    load_A(ldst + 1*STAGE_BYTES, gA + 128);
    load_B<NF>(ldst + 1*STAGE_BYTES, gB + 128); cp_commit();

    for (int kc = 0; kc < NCHUNK; kc++) {
        if (kc < NCHUNK - 1) asm volatile("cp.async.wait_group 1;" ::: "memory");
        else                 asm volatile("cp.async.wait_group 0;" ::: "memory");
        __syncthreads();
        const unsigned sA = a_base + (kc % NSTAGES) * STAGE_BYTES;
        const unsigned sB = b_base + (kc % NSTAGES) * STAGE_BYTES;
        const unsigned pdst = ldst + ((kc + 2) % NSTAGES) * STAGE_BYTES;
        const bool     pf   = (kc + 2 < NCHUNK);

        unsigned a[2][2][4];   // [buf][mf][frag] double-buffered across ks
        #pragma unroll
        for (int mf = 0; mf < 2; mf++)
            ldmatrix_x4(a[0][mf][0], a[0][mf][1], a[0][mf][2], a[0][mf][3],
                        sA + mf * (16 * ROW_BYTES));

        #pragma unroll
        for (int ks = 0; ks < 4; ks++) {
            const int ab = ks & 1;
            unsigned b[2][4];
            ldmatrix_x4(b[0][0], b[0][1], b[0][2], b[0][3], sB + ks * 32);
            if (ks < 3) {
                #pragma unroll
                for (int mf = 0; mf < 2; mf++)
                    ldmatrix_x4(a[ab^1][mf][0], a[ab^1][mf][1],
                                a[ab^1][mf][2], a[ab^1][mf][3],
                                sA + mf * (16 * ROW_BYTES) + (ks + 1) * 32);
            }
            #pragma unroll
            for (int nf = 0; nf < NF; nf++) {
                const int cur = nf & 1;
                if (nf < NF - 1)
                    ldmatrix_x4(b[cur^1][0], b[cur^1][1], b[cur^1][2], b[cur^1][3],
                                sB + (nf + 1) * (16 * ROW_BYTES) + ks * 32);
                #pragma unroll
                for (int mf = 0; mf < 2; mf++) {
                    mma_bf16(acc[mf][2*nf][0],   acc[mf][2*nf][1],
                             acc[mf][2*nf][2],   acc[mf][2*nf][3],
                             a[ab][mf][0], a[ab][mf][1], a[ab][mf][2], a[ab][mf][3],
                             b[cur][0], b[cur][1]);
                    mma_bf16(acc[mf][2*nf+1][0], acc[mf][2*nf+1][1],
                             acc[mf][2*nf+1][2], acc[mf][2*nf+1][3],
                             a[ab][mf][0], a[ab][mf][1], a[ab][mf][2], a[ab][mf][3],
                             b[cur][2], b[cur][3]);
                }
            }
            // spread prefetch: A-half after ks=0, B-half after ks=1
            if (ks == 0 && pf) load_A(pdst, gA + (kc + 2) * 128);
            if (ks == 1 && pf) { load_B<NF>(pdst, gB + (kc + 2) * 128); cp_commit(); }
        }
    }

    // ---------------- epilogue ----------------
    const int rq = lane >> 2;
    const int cq = (lane & 3) * 2;
    float rs[2][2] = {{0.f,0.f},{0.f,0.f}};
    float cs[2*NF][2];
    #pragma unroll
    for (int j = 0; j < 2*NF; j++) { cs[j][0] = 0.f; cs[j][1] = 0.f; }

    #pragma unroll
    for (int mf = 0; mf < 2; mf++) {
        #pragma unroll
        for (int j = 0; j < 2*NF; j++) {
            #pragma unroll
            for (int e = 0; e < 4; e++) {
                float a   = acc[mf][j][e];
                int r_g   = rb*128 + wm*32 + mf*16 + rq + ((e & 2) ? 8 : 0);
                int c_g   = cb*128 + col_off + wn*(NF*16) + j*8 + cq + (e & 1);
                float ev  = fexp2f(a * Y_SCALE);
                if (c_g == r_g) ev = 0.0f;
                rs[mf][e >> 1] += ev;
                cs[j][e & 1]   += ev;
                if (c_g == ((r_g + 4096) & 8191)) {
                    float pv = a * INVT;
                    atomicAdd(&g_pos[r_g], pv);
                    atomicAdd(&g_pos[c_g], pv);
                }
            }
        }
    }

    #pragma unroll
    for (int mf = 0; mf < 2; mf++) {
        #pragma unroll
        for (int h = 0; h < 2; h++) {
            float v = rs[mf][h];
            v += __shfl_xor_sync(0xFFFFFFFFu, v, 1);
            v += __shfl_xor_sync(0xFFFFFFFFu, v, 2);
            if ((lane & 3) == 0)
                atomicAdd(&g_rowsum[rb*128 + wm*32 + mf*16 + rq + h*8], v);
        }
    }

    if (mirror) {
        #pragma unroll
        for (int j = 0; j < 2*NF; j++) {
            #pragma unroll
            for (int par = 0; par < 2; par++) {
                float v = cs[j][par];
                v += __shfl_xor_sync(0xFFFFFFFFu, v, 4);
                v += __shfl_xor_sync(0xFFFFFFFFu, v, 8);
                v += __shfl_xor_sync(0xFFFFFFFFu, v, 16);
                if (lane < 4)
                    atomicAdd(&g_rowsum[cb*128 + col_off + wn*(NF*16) + j*8 + lane*2 + par], v);
            }
        }
    }
}

// ---------------------------------------------------------------------------
// Kernel 2: symmetric fused sim GEMM + exp row/col sums.
// bid<16: half-tiles of tiles (rb=0, cb=1..8), col halves. Else singles over
// tiles {0} U {9..2079}. 256 threads, warp tile 32x(NF*16).
// ---------------------------------------------------------------------------
__global__ void __launch_bounds__(256, 2) simexp_kernel() {
    extern __shared__ char smem[];
    unsigned smem_base = (unsigned)__cvta_generic_to_shared(smem);

    const int tid  = threadIdx.x;
    const int lane = tid & 31;
    const int wid  = tid >> 5;
    const int wm   = wid & 3;          // warp row 0..3 (32 rows each)
    const int wn   = wid >> 2;         // warp col 0..1

    const int bid = blockIdx.x;
    if (bid < 16) {
        // half tile: rb=0, cb=1+(bid>>1), cols [(bid&1)*64, +64)
        run_tile<2>(0, 1 + (bid >> 1), (bid & 1) * 64, true,
                    smem_base, tid, lane, wm, wn);
    } else {
        int s = bid - 16;
        int t = (s == 0) ? 0 : 8 + s;        // tiles {0} U {9..2079}
        int rb = (int)((129.0f - sqrtf(129.0f*129.0f - 8.0f*(float)t)) * 0.5f);
        if (rb > 63) rb = 63;
        if (rb < 0)  rb = 0;
        int off = rb*64 - rb*(rb-1)/2;
        while (off > t)                 { rb--; off = rb*64 - rb*(rb-1)/2; }
        while (off + (NBLK - rb) <= t)  { off += NBLK - rb; rb++; }
        int cb = rb + (t - off);
        run_tile<4>(rb, cb, 0, cb != rb, smem_base, tid, lane, wm, wn);
    }
}

// ---------------------------------------------------------------------------
// Kernel 3: loss partials -> atomicAdd into out (out zeroed by norm_kernel)
// ---------------------------------------------------------------------------
__global__ void __launch_bounds__(256) loss_kernel(float* __restrict__ out) {
    const int base = blockIdx.x * (NROWS / 32);
    float s = 0.0f;
    for (int i = threadIdx.x; i < NROWS / 32; i += 256) {
        int r = base + i;
        s += logf(g_rowsum[r]) - g_pos[r];
    }
    #pragma unroll
    for (int o = 16; o; o >>= 1) s += __shfl_xor_sync(0xFFFFFFFFu, s, o);
    __shared__ float red[8];
    if ((threadIdx.x & 31) == 0) red[threadIdx.x >> 5] = s;
    __syncthreads();
    if (threadIdx.x == 0) {
        float tot = red[0]+red[1]+red[2]+red[3]+red[4]+red[5]+red[6]+red[7];
        atomicAdd(out, tot * (1.0f / (float)NROWS));
    }
}

// ---------------------------------------------------------------------------
extern "C" void kernel_launch(void* const* d_in, const int* in_sizes, int n_in,
                              void* d_out, int out_size) {
    const float* v1 = (const float*)d_in[0];
    const float* v2 = (const float*)d_in[1];
    float* out = (float*)d_out;

    cudaFuncSetAttribute(simexp_kernel,
                         cudaFuncAttributeMaxDynamicSharedMemorySize, SMEM_TOTAL);

    norm_kernel<<<NROWS / 4, 128>>>(v1, v2, out);
    simexp_kernel<<<NJOBS, 256, SMEM_TOTAL>>>();
    loss_kernel<<<32, 256>>>(out);
}

// round 14
// speedup vs baseline: 1.1039x; 1.1039x over previous
#include <cuda_runtime.h>
#include <cuda_bf16.h>
#include <cstdint>

// ---------------- problem constants ----------------
#define BHALF 4096
#define NROWS 8192
#define DDIM  1024
#define INVT  10.0f
#define Y_SCALE 14.4269504088896341f   // INVT * log2(e)

// ---------------- tiling ----------------
#define KC 64                 // K elems per pipeline stage
#define ROW_BYTES 144         // 64 bf16 = 128B + 16B pad
#define A_BYTES (128 * ROW_BYTES)          // 18432
#define STAGE_BYTES (2 * A_BYTES)          // 36864
#define NSTAGES 3
#define SMEM_TOTAL (NSTAGES * STAGE_BYTES) // 110592
#define NBLK 64               // 8192 / 128
#define NTILES (NBLK * (NBLK + 1) / 2)     // 2080 upper-triangle tiles
// job packing: 8 double jobs (tiles 1..16) + 2064 singles = 2072 = 296*7
#define NJOBS 2072

__device__ __align__(16) __nv_bfloat16 g_fn[NROWS * DDIM];  // normalized bf16 (16MB)
__device__ float g_rowsum[NROWS];
__device__ float g_pos[NROWS];

// ---------------------------------------------------------------------------
__device__ __forceinline__ float fexp2f(float y) {
    float t = y + 12582912.0f;
    int   i = __float_as_int(t);
    float f = y - (t - 12582912.0f);
    float p = 1.33335581e-3f;
    p = fmaf(p, f, 9.61812910e-3f);
    p = fmaf(p, f, 5.55041086e-2f);
    p = fmaf(p, f, 2.40226507e-1f);
    p = fmaf(p, f, 6.93147182e-1f);
    p = fmaf(p, f, 1.0f);
    return p * __int_as_float((i + (127 - 0x4B400000)) << 23);
}

// ---------------------------------------------------------------------------
// Kernel 1: row L2-normalize -> bf16 (two-pass, low-register, high-occupancy).
// Also zeroes accumulators and out[0].
// ---------------------------------------------------------------------------
__global__ void __launch_bounds__(128) norm_kernel(const float* __restrict__ v1,
                                                   const float* __restrict__ v2,
                                                   float* __restrict__ out) {
    const int lane = threadIdx.x & 31;
    const int row  = blockIdx.x * 4 + (threadIdx.x >> 5);
    const float* src = (row < BHALF) ? (v1 + (size_t)row * DDIM)
                                     : (v2 + (size_t)(row - BHALF) * DDIM);
    const float4* src4 = reinterpret_cast<const float4*>(src);

    // pass 1: sum of squares (4-deep MLP, no data retention)
    float ss = 0.0f;
    #pragma unroll
    for (int i = 0; i < 2; i++) {
        float4 a = src4[lane + (4*i + 0) * 32];
        float4 b = src4[lane + (4*i + 1) * 32];
        float4 c = src4[lane + (4*i + 2) * 32];
        float4 d = src4[lane + (4*i + 3) * 32];
        ss += a.x*a.x + a.y*a.y + a.z*a.z + a.w*a.w;
        ss += b.x*b.x + b.y*b.y + b.z*b.z + b.w*b.w;
        ss += c.x*c.x + c.y*c.y + c.z*c.z + c.w*c.w;
        ss += d.x*d.x + d.y*d.y + d.z*d.z + d.w*d.w;
    }
    #pragma unroll
    for (int o = 16; o; o >>= 1) ss += __shfl_xor_sync(0xFFFFFFFFu, ss, o);
    float scale = 1.0f / fmaxf(sqrtf(ss), 1e-12f);

    // pass 2: reload (L2-hot), scale, store 8B bf16x4
    __nv_bfloat162* dst = reinterpret_cast<__nv_bfloat162*>(g_fn + (size_t)row * DDIM);
    #pragma unroll
    for (int i = 0; i < 8; i++) {
        float4 v = src4[lane + i * 32];
        __nv_bfloat162 h0, h1;
        h0.x = __float2bfloat16(v.x * scale); h0.y = __float2bfloat16(v.y * scale);
        h1.x = __float2bfloat16(v.z * scale); h1.y = __float2bfloat16(v.w * scale);
        int idx = lane + i * 32;
        dst[idx * 2 + 0] = h0;
        dst[idx * 2 + 1] = h1;
    }
    if (lane == 0) { g_rowsum[row] = 0.0f; g_pos[row] = 0.0f; }
    if (row == 0 && lane == 0) out[0] = 0.0f;
}

// ---------------------------------------------------------------------------
// PTX helpers
// ---------------------------------------------------------------------------
__device__ __forceinline__ void cp_async16(unsigned dst, const void* src) {
    asm volatile("cp.async.cg.shared.global [%0], [%1], 16;" :: "r"(dst), "l"(src) : "memory");
}
__device__ __forceinline__ void cp_commit() {
    asm volatile("cp.async.commit_group;" ::: "memory");
}
__device__ __forceinline__ void ldmatrix_x4(unsigned& r0, unsigned& r1,
                                            unsigned& r2, unsigned& r3, unsigned addr) {
    asm volatile("ldmatrix.sync.aligned.m8n8.x4.shared.b16 {%0,%1,%2,%3}, [%4];"
                 : "=r"(r0), "=r"(r1), "=r"(r2), "=r"(r3) : "r"(addr));
}
__device__ __forceinline__ void mma_bf16(float& d0, float& d1, float& d2, float& d3,
                                         unsigned a0, unsigned a1, unsigned a2, unsigned a3,
                                         unsigned b0, unsigned b1) {
    asm volatile("mma.sync.aligned.m16n8k16.row.col.f32.bf16.bf16.f32 "
                 "{%0,%1,%2,%3}, {%4,%5,%6,%7}, {%8,%9}, {%0,%1,%2,%3};"
                 : "+f"(d0), "+f"(d1), "+f"(d2), "+f"(d3)
                 : "r"(a0), "r"(a1), "r"(a2), "r"(a3), "r"(b0), "r"(b1));
}

// Half-chunk loads (A rows or B rows): 4 cp.async of 16B, hoisted pointers.
__device__ __forceinline__ void load_halfA(unsigned dstbase, const char* pA) {
    #pragma unroll
    for (int it = 0; it < 4; it++)
        cp_async16(dstbase + it * (32 * ROW_BYTES), pA + (size_t)it * 65536);
}
__device__ __forceinline__ void load_halfB(unsigned dstbase, const char* pB) {
    #pragma unroll
    for (int it = 0; it < 4; it++)
        cp_async16(dstbase + A_BYTES + it * (32 * ROW_BYTES), pB + (size_t)it * 65536);
}

// ---------------------------------------------------------------------------
// Kernel 2: symmetric fused sim GEMM + exp row/col sums.
// grid NJOBS: bid<8 = double job (rb=0, cb=1+2*bid, 2 sub-tiles);
// else single job over remapped tile index. 256 threads, warp tile 32x64.
// ---------------------------------------------------------------------------
__global__ void __launch_bounds__(256, 2) simexp_kernel() {
    extern __shared__ char smem[];
    unsigned smem_base = (unsigned)__cvta_generic_to_shared(smem);

    const int tid  = threadIdx.x;
    const int lane = tid & 31;
    const int wid  = tid >> 5;
    const int wm   = wid & 3;          // warp row 0..3 (32 rows each)
    const int wn   = wid >> 2;         // warp col 0..1 (64 cols each)

    // ---- job decode ----
    const int bid = blockIdx.x;
    int rb, cb0, nsub;
    if (bid < 8) {
        rb = 0; cb0 = 1 + bid * 2; nsub = 2;
    } else {
        int s = bid - 8;
        int t = (s == 0) ? 0 : 16 + s;       // tiles {0} U {17..2079}
        int r = (int)((129.0f - sqrtf(129.0f*129.0f - 8.0f*(float)t)) * 0.5f);
        if (r > 63) r = 63;
        if (r < 0)  r = 0;
        int off = r*64 - r*(r-1)/2;
        while (off > t)                { r--; off = r*64 - r*(r-1)/2; }
        while (off + (NBLK - r) <= t)  { off += NBLK - r; r++; }
        rb = r; cb0 = r + (t - off); nsub = 1;
    }

    // ---- hoisted per-thread load addressing ----
    const int rA   = tid >> 3;             // base row 0..31 (it adds 32)
    const int p16  = (tid & 7) * 16;       // 16B chunk within 128B row
    const char* gA = (const char*)g_fn
                   + ((size_t)(rb * 128 + rA) * DDIM) * 2 + p16;
    const unsigned ldst = smem_base + rA * ROW_BYTES + p16;

    // ldmatrix lane base addresses (stage-relative)
    const unsigned a_base = smem_base + (wm*32 + (lane & 15)) * ROW_BYTES + (lane >> 4) * 16;
    const unsigned b_base = smem_base + A_BYTES
                          + (wn*64 + (lane & 7) + ((lane >> 4) << 3)) * ROW_BYTES
                          + ((lane >> 3) & 1) * 16;

    const int rq = lane >> 2;      // 0..7
    const int cq = (lane & 3) * 2; // 0,2,4,6
    const int NCHUNK = DDIM / KC;  // 16

    #pragma unroll 1
    for (int sub = 0; sub < nsub; sub++) {
        const int cb = cb0 + sub;
        const bool is_diag = (cb == rb);
        const bool is_pos  = (cb == rb + 32);
        const char* gB = (const char*)g_fn
                       + ((size_t)(cb * 128 + rA) * DDIM) * 2 + p16;

        float acc[2][8][4];
        #pragma unroll
        for (int mf = 0; mf < 2; mf++)
            #pragma unroll
            for (int j = 0; j < 8; j++)
                #pragma unroll
                for (int e = 0; e < 4; e++) acc[mf][j][e] = 0.0f;

        __syncthreads();   // protect stage reuse across sub-tiles
        load_halfA(ldst + 0*STAGE_BYTES, gA);
        load_halfB(ldst + 0*STAGE_BYTES, gB);       cp_commit();
        load_halfA(ldst + 1*STAGE_BYTES, gA + 128);
        load_halfB(ldst + 1*STAGE_BYTES, gB + 128); cp_commit();

        for (int kc = 0; kc < NCHUNK; kc++) {
            if (kc < NCHUNK - 1) asm volatile("cp.async.wait_group 1;" ::: "memory");
            else                 asm volatile("cp.async.wait_group 0;" ::: "memory");
            __syncthreads();
            const unsigned sA = a_base + (kc % NSTAGES) * STAGE_BYTES;
            const unsigned sB = b_base + (kc % NSTAGES) * STAGE_BYTES;
            const unsigned pdst = ldst + ((kc + 2) % NSTAGES) * STAGE_BYTES;
            const bool     pf   = (kc + 2 < NCHUNK);

            unsigned a[2][2][4];   // [buf][mf][frag] double-buffered across ks
            #pragma unroll
            for (int mf = 0; mf < 2; mf++)
                ldmatrix_x4(a[0][mf][0], a[0][mf][1], a[0][mf][2], a[0][mf][3],
                            sA + mf * (16 * ROW_BYTES));

            #pragma unroll
            for (int ks = 0; ks < 4; ks++) {
                const int ab = ks & 1;
                unsigned b[2][4];
                ldmatrix_x4(b[0][0], b[0][1], b[0][2], b[0][3], sB + ks * 32);
                if (ks < 3) {
                    #pragma unroll
                    for (int mf = 0; mf < 2; mf++)
                        ldmatrix_x4(a[ab^1][mf][0], a[ab^1][mf][1],
                                    a[ab^1][mf][2], a[ab^1][mf][3],
                                    sA + mf * (16 * ROW_BYTES) + (ks + 1) * 32);
                }
                #pragma unroll
                for (int nf = 0; nf < 4; nf++) {
                    const int cur = nf & 1;
                    if (nf < 3)
                        ldmatrix_x4(b[cur^1][0], b[cur^1][1], b[cur^1][2], b[cur^1][3],
                                    sB + (nf + 1) * (16 * ROW_BYTES) + ks * 32);
                    #pragma unroll
                    for (int mf = 0; mf < 2; mf++) {
                        mma_bf16(acc[mf][2*nf][0],   acc[mf][2*nf][1],
                                 acc[mf][2*nf][2],   acc[mf][2*nf][3],
                                 a[ab][mf][0], a[ab][mf][1], a[ab][mf][2], a[ab][mf][3],
                                 b[cur][0], b[cur][1]);
                        mma_bf16(acc[mf][2*nf+1][0], acc[mf][2*nf+1][1],
                                 acc[mf][2*nf+1][2], acc[mf][2*nf+1][3],
                                 a[ab][mf][0], a[ab][mf][1], a[ab][mf][2], a[ab][mf][3],
                                 b[cur][2], b[cur][3]);
                    }
                }
                // spread prefetch: A-half after ks=0, B-half after ks=1
                if (ks == 0 && pf) load_halfA(pdst, gA + (kc + 2) * 128);
                if (ks == 1 && pf) { load_halfB(pdst, gB + (kc + 2) * 128); cp_commit(); }
            }
        }

        // ---------------- epilogue ----------------
        float rs[2][2] = {{0.f,0.f},{0.f,0.f}};
        float cs[8][2];
        #pragma unroll
        for (int j = 0; j < 8; j++) { cs[j][0] = 0.f; cs[j][1] = 0.f; }

        #pragma unroll
        for (int mf = 0; mf < 2; mf++) {
            #pragma unroll
            for (int j = 0; j < 8; j++) {
                #pragma unroll
                for (int e = 0; e < 4; e++) {
                    float a  = acc[mf][j][e];
                    int r_local = wm*32 + mf*16 + rq + ((e & 2) ? 8 : 0);
                    int c_local = wn*64 + j*8 + cq + (e & 1);
                    float ev = fexp2f(a * Y_SCALE);
                    if (is_diag && r_local == c_local) ev = 0.0f;
                    rs[mf][e >> 1] += ev;
                    cs[j][e & 1]   += ev;
                    if (is_pos && r_local == c_local) {
                        float pv = a * INVT;
                        atomicAdd(&g_pos[rb*128 + r_local], pv);
                        atomicAdd(&g_pos[cb*128 + c_local], pv);
                    }
                }
            }
        }

        #pragma unroll
        for (int mf = 0; mf < 2; mf++) {
            #pragma unroll
            for (int h = 0; h < 2; h++) {
                float v = rs[mf][h];
                v += __shfl_xor_sync(0xFFFFFFFFu, v, 1);
                v += __shfl_xor_sync(0xFFFFFFFFu, v, 2);
                if ((lane & 3) == 0)
                    atomicAdd(&g_rowsum[rb*128 + wm*32 + mf*16 + rq + h*8], v);
            }
        }

        if (!is_diag) {
            #pragma unroll
            for (int j = 0; j < 8; j++) {
                #pragma unroll
                for (int par = 0; par < 2; par++) {
                    float v = cs[j][par];
                    v += __shfl_xor_sync(0xFFFFFFFFu, v, 4);
                    v += __shfl_xor_sync(0xFFFFFFFFu, v, 8);
                    v += __shfl_xor_sync(0xFFFFFFFFu, v, 16);
                    if (lane < 4)
                        atomicAdd(&g_rowsum[cb*128 + wn*64 + j*8 + lane*2 + par], v);
                }
            }
        }
    }
}

// ---------------------------------------------------------------------------
// Kernel 3: loss partials -> atomicAdd into out (out zeroed by norm_kernel)
// ---------------------------------------------------------------------------
__global__ void __launch_bounds__(256) loss_kernel(float* __restrict__ out) {
    const int base = blockIdx.x * (NROWS / 32);
    float s = 0.0f;
    for (int i = threadIdx.x; i < NROWS / 32; i += 256) {
        int r = base + i;
        s += logf(g_rowsum[r]) - g_pos[r];
    }
    #pragma unroll
    for (int o = 16; o; o >>= 1) s += __shfl_xor_sync(0xFFFFFFFFu, s, o);
    __shared__ float red[8];
    if ((threadIdx.x & 31) == 0) red[threadIdx.x >> 5] = s;
    __syncthreads();
    if (threadIdx.x == 0) {
        float tot = red[0]+red[1]+red[2]+red[3]+red[4]+red[5]+red[6]+red[7];
        atomicAdd(out, tot * (1.0f / (float)NROWS));
    }
}

// ---------------------------------------------------------------------------
extern "C" void kernel_launch(void* const* d_in, const int* in_sizes, int n_in,
                              void* d_out, int out_size) {
    const float* v1 = (const float*)d_in[0];
    const float* v2 = (const float*)d_in[1];
    float* out = (float*)d_out;

    cudaFuncSetAttribute(simexp_kernel,
                         cudaFuncAttributeMaxDynamicSharedMemorySize, SMEM_TOTAL);

    norm_kernel<<<NROWS / 4, 128>>>(v1, v2, out);
    simexp_kernel<<<NJOBS, 256, SMEM_TOTAL>>>();
    loss_kernel<<<32, 256>>>(out);
}